// round 16
// baseline (speedup 1.0000x reference)
#include <cuda_runtime.h>
#include <cuda_fp16.h>
#include <cstdint>

// ---------------- problem constants ----------------
#define MDIM 65536      // B*S
#define KDIM 768        // D
#define NDIM 2304      // 3*D
#define RNK  4

#define BM 128
#define BN 256
#define BK 32           // halves per K-step
#define KITERS (KDIM / BK)   // 24
#define STAGES 4

// smem stage layout: A 128 rows x 80B (32 halves + 16B pad), B 256 rows x 80B
#define AROW_B   80
#define A_BYTES  (128 * AROW_B)      // 10240
#define B_BYTES  (256 * AROW_B)      // 20480
#define STAGE_B  (A_BYTES + B_BYTES) // 30720
#define SMEM_TOTAL (STAGES * STAGE_B) // 122880

// ---------------- device scratch (no allocations allowed) ----------------
__device__ __half g_Wh[(size_t)NDIM * KDIM];   // folded fp16 W_eff (3.4 MB)

// ---------------- helpers ----------------
__device__ __forceinline__ uint32_t smem_u32(const void* p) {
    return (uint32_t)__cvta_generic_to_shared(p);
}

__device__ __forceinline__ void cp_async16(uint32_t s, const void* g) {
    asm volatile("cp.async.cg.shared.global [%0], [%1], 16;" :: "r"(s), "l"(g));
}
#define CP_COMMIT() asm volatile("cp.async.commit_group;" ::: "memory")

#define LDSM_X4(r0, r1, r2, r3, addr) \
    asm volatile("ldmatrix.sync.aligned.m8n8.x4.shared.b16 {%0,%1,%2,%3}, [%4];" \
        : "=r"(r0), "=r"(r1), "=r"(r2), "=r"(r3) : "r"(addr))

// fp16-accumulate MMA (double-rate HMMA, rt~8/SMSP on sm_103a)
#define MMA16816_F16(d, a0, a1, a2, a3, b0, b1) \
    asm volatile("mma.sync.aligned.m16n8k16.row.col.f16.f16.f16.f16 " \
        "{%0,%1}, {%2,%3,%4,%5}, {%6,%7}, {%0,%1};" \
        : "+r"((d)[0]), "+r"((d)[1]) \
        : "r"(a0), "r"(a1), "r"(a2), "r"(a3), "r"(b0), "r"(b1))

// convert 8 fp32 -> 8 fp16, store 16B to smem
__device__ __forceinline__ void sts_a16(uint32_t dst, float4 p0, float4 p1) {
    __half2 h0 = __floats2half2_rn(p0.x, p0.y);
    __half2 h1 = __floats2half2_rn(p0.z, p0.w);
    __half2 h2 = __floats2half2_rn(p1.x, p1.y);
    __half2 h3 = __floats2half2_rn(p1.z, p1.w);
    asm volatile("st.shared.v4.b32 [%0], {%1,%2,%3,%4};" :: "r"(dst),
        "r"(*reinterpret_cast<uint32_t*>(&h0)), "r"(*reinterpret_cast<uint32_t*>(&h1)),
        "r"(*reinterpret_cast<uint32_t*>(&h2)), "r"(*reinterpret_cast<uint32_t*>(&h3))
        : "memory");
}

// ---------------- prep kernel (fold LoRA into W, fp16) ----------------
__global__ void prep_w_kernel(const float* __restrict__ W,
                              const float* __restrict__ Aq, const float* __restrict__ Bq,
                              const float* __restrict__ Av, const float* __restrict__ Bv,
                              const float* __restrict__ s0) {
    int idx = blockIdx.x * 256 + threadIdx.x;   // exact: NDIM*KDIM
    int e = idx / KDIM;
    int d = idx - e * KDIM;
    float w = W[idx];
    float s = s0[0];
    if (e < KDIM) {                              // q slice
        float acc = 0.f;
#pragma unroll
        for (int r = 0; r < RNK; r++) acc += Aq[r * KDIM + d] * Bq[e * RNK + r];
        w = fmaf(s, acc, w);
    } else if (e >= 2 * KDIM) {                  // v slice
        int e2 = e - 2 * KDIM;
        float acc = 0.f;
#pragma unroll
        for (int r = 0; r < RNK; r++) acc += Av[r * KDIM + d] * Bv[e2 * RNK + r];
        w = fmaf(s, acc, w);
    }
    g_Wh[idx] = __float2half_rn(w);
}

// --- GEMM: 256 thr, 8 warps (2m x 4n), warp tile 64x64, fp16 acc 2 chains,
// --- fused fp32->fp16 A path, B-frag pipelined. 256-reg/thread budget.
__global__ __launch_bounds__(256, 1)
void gemm_f16_kernel(const float* __restrict__ X, const __half* __restrict__ W,
                     const float* __restrict__ bias, float* __restrict__ out) {
    extern __shared__ char smem[];
    uint32_t sb = smem_u32(smem);
    int tid = threadIdx.x;
    int lane = tid & 31;
    int wid = tid >> 5;
    int warp_m = wid & 1;     // 2 m-warps (64 rows)
    int warp_n = wid >> 1;    // 4 n-warps (64 cols)

    int n0 = blockIdx.x * BN;   // 9 n-tiles fast-varying (X L2 reuse)
    int m0 = blockIdx.y * BM;

    // ---- per-thread load geometry ----
    int arow = tid >> 2, ac = tid & 3;   // arow 0..63; rows arow, arow+64
    const float* aSrc = X + (size_t)(m0 + arow) * KDIM + ac * 8;
    uint32_t aDst = sb + arow * AROW_B + ac * 16;

    // B: 4 rows per thread (+0,64,128,192), cp.async 16B each
    const __half* bSrc = W + (size_t)(n0 + arow) * KDIM + ac * 8;
    uint32_t bDst = sb + A_BYTES + arow * AROW_B + ac * 16;

    // ---- ldmatrix lane addresses ----
    uint32_t aLds = sb + (warp_m * 64 + (lane & 15)) * AROW_B + ((lane >> 4) * 16);
    int t_ = lane >> 3;
    uint32_t bLds = sb + A_BYTES + (warp_n * 64 + (lane & 7) + (t_ >> 1) * 8) * AROW_B
                    + (t_ & 1) * 16;

    // fp16 accumulators: 2 K-chains x 4 mi x 8 nj (128 regs)
    uint32_t acch[2][4][8][2];
#pragma unroll
    for (int c = 0; c < 2; c++)
#pragma unroll
        for (int mi = 0; mi < 4; mi++)
#pragma unroll
            for (int nj = 0; nj < 8; nj++) {
                acch[c][mi][nj][0] = 0u;
                acch[c][mi][nj][1] = 0u;
            }

    // ---- prologue ----
    // B stages 0..2 via cp.async (3 commit groups)
#pragma unroll
    for (int s = 0; s < STAGES - 1; s++) {
        uint32_t so = s * STAGE_B;
#pragma unroll
        for (int t = 0; t < 4; t++)
            cp_async16(bDst + so + t * 64 * AROW_B,
                       bSrc + (size_t)t * 64 * KDIM + s * BK);
        CP_COMMIT();
    }
    // A stage 0 (both row-halves): LDG fp32 -> cvt -> STS; preload stage 1
    float4 pa[2][2];
    {
        const float* ap0 = aSrc;
        const float* ap1 = aSrc + (size_t)64 * KDIM;
        sts_a16(aDst,
                *reinterpret_cast<const float4*>(ap0),
                *reinterpret_cast<const float4*>(ap0 + 4));
        sts_a16(aDst + 64 * AROW_B,
                *reinterpret_cast<const float4*>(ap1),
                *reinterpret_cast<const float4*>(ap1 + 4));
        pa[0][0] = *reinterpret_cast<const float4*>(ap0 + BK);
        pa[0][1] = *reinterpret_cast<const float4*>(ap0 + BK + 4);
        pa[1][0] = *reinterpret_cast<const float4*>(ap1 + BK);
        pa[1][1] = *reinterpret_cast<const float4*>(ap1 + BK + 4);
    }

    for (int k = 0; k < KITERS; k++) {
        // STS A(k+1) from reg buffer (slot (k+1)&3 drained since k-3)
        {
            uint32_t d = aDst + ((k + 1) & 3) * STAGE_B;
            sts_a16(d, pa[0][0], pa[0][1]);
            sts_a16(d + 64 * AROW_B, pa[1][0], pa[1][1]);
        }

        asm volatile("cp.async.wait_group 2;" ::: "memory");
        __syncthreads();

        // LDG A stage k+2 (clamped tail re-read harmless)
        {
            int ak = (k + 2 < KITERS) ? (k + 2) : (KITERS - 1);
            const float* ap0 = aSrc + ak * BK;
            const float* ap1 = ap0 + (size_t)64 * KDIM;
            pa[0][0] = *reinterpret_cast<const float4*>(ap0);
            pa[0][1] = *reinterpret_cast<const float4*>(ap0 + 4);
            pa[1][0] = *reinterpret_cast<const float4*>(ap1);
            pa[1][1] = *reinterpret_cast<const float4*>(ap1 + 4);
        }

        // cp.async B stage k+3
        int kn = k + STAGES - 1;
        if (kn < KITERS) {
            uint32_t so = (kn & (STAGES - 1)) * STAGE_B;
#pragma unroll
            for (int t = 0; t < 4; t++)
                cp_async16(bDst + so + t * 64 * AROW_B,
                           bSrc + (size_t)t * 64 * KDIM + kn * BK);
        }
        CP_COMMIT();

        // ---- compute stage k: B-frag pipelined ----
        uint32_t so = (k & (STAGES - 1)) * STAGE_B;
        uint32_t aB = aLds + so;
        uint32_t bB = bLds + so;
        uint32_t (*acc)[8][2] = (k < KITERS / 2) ? acch[0] : acch[1];
#pragma unroll
        for (int ks = 0; ks < 2; ks++) {
            uint32_t a[4][4];
#pragma unroll
            for (int mi = 0; mi < 4; mi++)
                LDSM_X4(a[mi][0], a[mi][1], a[mi][2], a[mi][3],
                        aB + mi * (16 * AROW_B) + ks * 32);
            uint32_t bb[2][4];
            LDSM_X4(bb[0][0], bb[0][1], bb[0][2], bb[0][3], bB + ks * 32);
#pragma unroll
            for (int p = 0; p < 4; p++) {
                if (p < 3)
                    LDSM_X4(bb[(p + 1) & 1][0], bb[(p + 1) & 1][1],
                            bb[(p + 1) & 1][2], bb[(p + 1) & 1][3],
                            bB + (p + 1) * (16 * AROW_B) + ks * 32);
                uint32_t* bc = bb[p & 1];
#pragma unroll
                for (int mi = 0; mi < 4; mi++) {
                    MMA16816_F16(acc[mi][2 * p],     a[mi][0], a[mi][1], a[mi][2], a[mi][3], bc[0], bc[1]);
                    MMA16816_F16(acc[mi][2 * p + 1], a[mi][0], a[mi][1], a[mi][2], a[mi][3], bc[2], bc[3]);
                }
            }
        }
    }

    // ---- epilogue: combine chains in fp32, add bias, store ----
#pragma unroll
    for (int nj = 0; nj < 8; nj++) {
        int c = n0 + warp_n * 64 + nj * 8 + 2 * (lane & 3);
        float2 bb = *reinterpret_cast<const float2*>(bias + c);
#pragma unroll
        for (int mi = 0; mi < 4; mi++) {
            int r = m0 + warp_m * 64 + mi * 16 + (lane >> 2);
            float2 c00 = __half22float2(*reinterpret_cast<__half2*>(&acch[0][mi][nj][0]));
            float2 c01 = __half22float2(*reinterpret_cast<__half2*>(&acch[0][mi][nj][1]));
            float2 c10 = __half22float2(*reinterpret_cast<__half2*>(&acch[1][mi][nj][0]));
            float2 c11 = __half22float2(*reinterpret_cast<__half2*>(&acch[1][mi][nj][1]));
            float2 v0, v1;
            v0.x = c00.x + c10.x + bb.x;
            v0.y = c00.y + c10.y + bb.y;
            v1.x = c01.x + c11.x + bb.x;
            v1.y = c01.y + c11.y + bb.y;
            *reinterpret_cast<float2*>(out + (size_t)r * NDIM + c) = v0;
            *reinterpret_cast<float2*>(out + (size_t)(r + 8) * NDIM + c) = v1;
        }
    }
}

// ---------------- launch ----------------
extern "C" void kernel_launch(void* const* d_in, const int* in_sizes, int n_in,
                              void* d_out, int out_size) {
    (void)in_sizes; (void)n_in; (void)out_size;
    const float* x   = (const float*)d_in[0];
    const float* Wq  = (const float*)d_in[1];
    const float* b   = (const float*)d_in[2];
    const float* Aq  = (const float*)d_in[3];
    const float* Bq  = (const float*)d_in[4];
    const float* Av  = (const float*)d_in[5];
    const float* Bv  = (const float*)d_in[6];
    const float* s0  = (const float*)d_in[7];
    float* out = (float*)d_out;

    __half* wh;
    cudaGetSymbolAddress((void**)&wh, g_Wh);

    prep_w_kernel<<<(NDIM * KDIM) / 256, 256>>>(Wq, Aq, Bq, Av, Bv, s0);

    cudaFuncSetAttribute(gemm_f16_kernel,
                         cudaFuncAttributeMaxDynamicSharedMemorySize, SMEM_TOTAL);
    gemm_f16_kernel<<<dim3(NDIM / BN, MDIM / BM, 1), 256, SMEM_TOTAL>>>(
        x, wh, b, out);
}